// round 3
// baseline (speedup 1.0000x reference)
#include <cuda_runtime.h>
#include <cstdint>

// Palette packed keys: (r<<16)|(g<<8)|b  -> class id == index
// 0: 0x000000  1: 0x800000  2: 0x804080  3: 0xC000C0
// 4: 0x008000  5: 0x808000  6: 0x404000  7: 0x400080

__device__ __forceinline__ float classify(int r, int g, int b) {
    unsigned key = ((unsigned)r << 16) | ((unsigned)g << 8) | (unsigned)b;
    int c = 0;
    c += (key == 0x800000u) ? 1 : 0;
    c += (key == 0x804080u) ? 2 : 0;
    c += (key == 0xC000C0u) ? 3 : 0;
    c += (key == 0x008000u) ? 4 : 0;
    c += (key == 0x808000u) ? 5 : 0;
    c += (key == 0x404000u) ? 6 : 0;
    c += (key == 0x400080u) ? 7 : 0;
    return (float)c;  // unmatched (incl. key 0) -> 0
}

__global__ void __launch_bounds__(256)
uavid_vec4_f32_kernel(const int4* __restrict__ rp,
                      const int4* __restrict__ gp,
                      const int4* __restrict__ bp,
                      float4* __restrict__ out,
                      int n4) {
    int i = blockIdx.x * blockDim.x + threadIdx.x;
    if (i >= n4) return;
    int4 r = rp[i];
    int4 g = gp[i];
    int4 b = bp[i];
    float4 o;
    o.x = classify(r.x, g.x, b.x);
    o.y = classify(r.y, g.y, b.y);
    o.z = classify(r.z, g.z, b.z);
    o.w = classify(r.w, g.w, b.w);
    out[i] = o;
}

__global__ void uavid_tail_f32_kernel(const int* __restrict__ rp,
                                      const int* __restrict__ gp,
                                      const int* __restrict__ bp,
                                      float* __restrict__ out,
                                      int start, int hw) {
    int i = start + blockIdx.x * blockDim.x + threadIdx.x;
    if (i >= hw) return;
    out[i] = classify(rp[i], gp[i], bp[i]);
}

extern "C" void kernel_launch(void* const* d_in, const int* in_sizes, int n_in,
                              void* d_out, int out_size) {
    const int* t = (const int*)d_in[0];
    int n  = in_sizes[0];     // 3 * H * W
    int hw = n / 3;           // H * W
    const int* rp = t;
    const int* gp = t + hw;
    const int* bp = t + 2 * hw;

    int n4  = hw >> 2;        // vectorized pixels (groups of 4)
    int rem = hw & 3;

    if (n4 > 0) {
        int threads = 256;
        int blocks  = (n4 + threads - 1) / threads;
        uavid_vec4_f32_kernel<<<blocks, threads>>>(
            (const int4*)rp, (const int4*)gp, (const int4*)bp,
            (float4*)d_out, n4);
    }
    if (rem > 0) {
        uavid_tail_f32_kernel<<<1, 256>>>(rp, gp, bp,
                                          (float*)d_out, n4 << 2, hw);
    }
}

// round 4
// speedup vs baseline: 1.0014x; 1.0014x over previous
#include <cuda_runtime.h>
#include <cstdint>

// Palette packed keys: (r<<16)|(g<<8)|b  -> class id == index
// 0: 0x000000  1: 0x800000  2: 0x804080  3: 0xC000C0
// 4: 0x008000  5: 0x808000  6: 0x404000  7: 0x400080

__device__ __forceinline__ float classify(int r, int g, int b) {
    unsigned key = ((unsigned)r << 16) | ((unsigned)g << 8) | (unsigned)b;
    int c = 0;
    c += (key == 0x800000u) ? 1 : 0;
    c += (key == 0x804080u) ? 2 : 0;
    c += (key == 0xC000C0u) ? 3 : 0;
    c += (key == 0x008000u) ? 4 : 0;
    c += (key == 0x808000u) ? 5 : 0;
    c += (key == 0x404000u) ? 6 : 0;
    c += (key == 0x400080u) ? 7 : 0;
    return (float)c;  // unmatched (incl. key 0) -> 0
}

__device__ __forceinline__ float4 classify4(int4 r, int4 g, int4 b) {
    float4 o;
    o.x = classify(r.x, g.x, b.x);
    o.y = classify(r.y, g.y, b.y);
    o.z = classify(r.z, g.z, b.z);
    o.w = classify(r.w, g.w, b.w);
    return o;
}

// 8 pixels per thread: 6 independent 16B loads (front-batched), 2 float4 stores.
__global__ void __launch_bounds__(256)
uavid_vec8_f32_kernel(const int4* __restrict__ rp,
                      const int4* __restrict__ gp,
                      const int4* __restrict__ bp,
                      float4* __restrict__ out,
                      int n4) {
    int i = (blockIdx.x * blockDim.x + threadIdx.x) * 2;
    if (i + 1 < n4) {
        // Front-batch all 6 loads for max MLP
        int4 r0 = __ldcs(&rp[i]);
        int4 r1 = __ldcs(&rp[i + 1]);
        int4 g0 = __ldcs(&gp[i]);
        int4 g1 = __ldcs(&gp[i + 1]);
        int4 b0 = __ldcs(&bp[i]);
        int4 b1 = __ldcs(&bp[i + 1]);
        __stcs(&out[i],     classify4(r0, g0, b0));
        __stcs(&out[i + 1], classify4(r1, g1, b1));
    } else if (i < n4) {
        int4 r0 = __ldcs(&rp[i]);
        int4 g0 = __ldcs(&gp[i]);
        int4 b0 = __ldcs(&bp[i]);
        __stcs(&out[i], classify4(r0, g0, b0));
    }
}

__global__ void uavid_tail_f32_kernel(const int* __restrict__ rp,
                                      const int* __restrict__ gp,
                                      const int* __restrict__ bp,
                                      float* __restrict__ out,
                                      int start, int hw) {
    int i = start + blockIdx.x * blockDim.x + threadIdx.x;
    if (i >= hw) return;
    out[i] = classify(rp[i], gp[i], bp[i]);
}

extern "C" void kernel_launch(void* const* d_in, const int* in_sizes, int n_in,
                              void* d_out, int out_size) {
    const int* t = (const int*)d_in[0];
    int n  = in_sizes[0];     // 3 * H * W
    int hw = n / 3;           // H * W
    const int* rp = t;
    const int* gp = t + hw;
    const int* bp = t + 2 * hw;

    int n4  = hw >> 2;        // vectorized pixel-quads
    int rem = hw & 3;

    if (n4 > 0) {
        int threads = 256;
        // each thread handles 2 quads (8 pixels)
        int quads_per_block = threads * 2;
        int blocks = (n4 + quads_per_block - 1) / quads_per_block;
        uavid_vec8_f32_kernel<<<blocks, threads>>>(
            (const int4*)rp, (const int4*)gp, (const int4*)bp,
            (float4*)d_out, n4);
    }
    if (rem > 0) {
        uavid_tail_f32_kernel<<<1, 256>>>(rp, gp, bp,
                                          (float*)d_out, n4 << 2, hw);
    }
}